// round 1
// baseline (speedup 1.0000x reference)
#include <cuda_runtime.h>
#include <cstdint>

#define B_  8
#define T_  2048
#define D_  544
#define H_  8
#define DK_ 64
#define DV_ 128
#define KDIM_ 512
#define VDIM_ 1024
#define HID_ 1632
#define NTOK (B_*T_)          // 16384
#define M1   3088             // 512+512+1024+8+8+1024 fused out dims

// ---------------- scratch (device globals; no runtime alloc allowed) --------
static __device__ float g_h   [NTOK * D_];
static __device__ float g_wcat[M1 * D_];
static __device__ float g_c1  [(size_t)NTOK * M1];
static __device__ float g_q   [(size_t)NTOK * KDIM_];
static __device__ float g_k   [(size_t)NTOK * KDIM_];
static __device__ float g_v   [(size_t)NTOK * VDIM_];
static __device__ float g_beta[NTOK * H_];
static __device__ float g_g   [NTOK * H_];
static __device__ float g_o   [(size_t)NTOK * VDIM_];
static __device__ float g_og  [(size_t)NTOK * VDIM_];
static __device__ float g_xmid[NTOK * D_];
static __device__ float g_h2  [NTOK * D_];
static __device__ float g_m2  [(size_t)NTOK * HID_];

// ---------------- pack fused weight matrix [3088 x 544] ---------------------
__global__ void pack_wcat(const float* __restrict__ Wq, const float* __restrict__ Wk,
                          const float* __restrict__ Wv, const float* __restrict__ Wb,
                          const float* __restrict__ Wa, const float* __restrict__ Wg) {
    int idx = blockIdx.x * blockDim.x + threadIdx.x;
    if (idx >= M1 * D_) return;
    int row = idx / D_, col = idx % D_;
    float v;
    if      (row < 512)  v = Wq[row * D_ + col];
    else if (row < 1024) v = Wk[(row - 512) * D_ + col];
    else if (row < 2048) v = Wv[(row - 1024) * D_ + col];
    else if (row < 2056) v = Wb[(row - 2048) * D_ + col];
    else if (row < 2064) v = Wa[(row - 2056) * D_ + col];
    else                 v = Wg[(row - 2064) * D_ + col];
    g_wcat[idx] = v;
}

// ---------------- parameter-free RMSNorm over D=544 -------------------------
__global__ void rms_kernel(const float* __restrict__ x, float* __restrict__ y) {
    int row = blockIdx.x;
    int tid = threadIdx.x;          // blockDim = 544 (17 warps)
    float v = x[(size_t)row * D_ + tid];
    float s = v * v;
    #pragma unroll
    for (int o = 16; o; o >>= 1) s += __shfl_xor_sync(0xffffffffu, s, o);
    __shared__ float ws[17];
    if ((tid & 31) == 0) ws[tid >> 5] = s;
    __syncthreads();
    if (tid < 32) {
        float t = (tid < 17) ? ws[tid] : 0.f;
        #pragma unroll
        for (int o = 16; o; o >>= 1) t += __shfl_xor_sync(0xffffffffu, t, o);
        if (tid == 0) ws[0] = t;
    }
    __syncthreads();
    float scale = rsqrtf(ws[0] * (1.0f / (float)D_) + 1e-6f);
    y[(size_t)row * D_ + tid] = v * scale;
}

// ---------------- SGEMM: C[M,N] = A[M,K] * B[N,K]^T  (both K-contiguous) ----
// 128x128 tile, BK=8, 256 threads, 8x8 per thread. Epilogue modes:
//   0: C = acc
//   1: C = res + scale[col] * acc
//   2: C = relu(acc)^2
__global__ void __launch_bounds__(256)
sgemm_kernel(const float* __restrict__ A, const float* __restrict__ B,
             float* __restrict__ C, int N, int K, int mode,
             const float* __restrict__ res, const float* __restrict__ scale) {
    __shared__ float sA[8 * 132];
    __shared__ float sB[8 * 132];
    const int tid = threadIdx.x;
    const int rowBase = blockIdx.y * 128;
    const int colBase = blockIdx.x * 128;

    const int loadRow = tid >> 1;           // 0..127
    const int loadK   = (tid & 1) * 4;      // 0 or 4
    const float* Aptr = A + (size_t)(rowBase + loadRow) * K + loadK;
    const int bcol = colBase + loadRow;
    const float* Bptr = B + (size_t)bcol * K + loadK;
    const bool bvalid = (bcol < N);

    const int tx = tid & 15, ty = tid >> 4;
    float acc[8][8];
    #pragma unroll
    for (int i = 0; i < 8; i++)
        #pragma unroll
        for (int j = 0; j < 8; j++) acc[i][j] = 0.f;

    for (int k0 = 0; k0 < K; k0 += 8) {
        float4 av = *(const float4*)(Aptr + k0);
        float4 bv = bvalid ? *(const float4*)(Bptr + k0) : make_float4(0.f, 0.f, 0.f, 0.f);
        sA[(loadK + 0) * 132 + loadRow] = av.x;
        sA[(loadK + 1) * 132 + loadRow] = av.y;
        sA[(loadK + 2) * 132 + loadRow] = av.z;
        sA[(loadK + 3) * 132 + loadRow] = av.w;
        sB[(loadK + 0) * 132 + loadRow] = bv.x;
        sB[(loadK + 1) * 132 + loadRow] = bv.y;
        sB[(loadK + 2) * 132 + loadRow] = bv.z;
        sB[(loadK + 3) * 132 + loadRow] = bv.w;
        __syncthreads();
        #pragma unroll
        for (int kk = 0; kk < 8; kk++) {
            float4 a0 = *(const float4*)&sA[kk * 132 + ty * 8];
            float4 a1 = *(const float4*)&sA[kk * 132 + ty * 8 + 4];
            float4 b0 = *(const float4*)&sB[kk * 132 + tx * 8];
            float4 b1 = *(const float4*)&sB[kk * 132 + tx * 8 + 4];
            float a[8] = {a0.x, a0.y, a0.z, a0.w, a1.x, a1.y, a1.z, a1.w};
            float b[8] = {b0.x, b0.y, b0.z, b0.w, b1.x, b1.y, b1.z, b1.w};
            #pragma unroll
            for (int i = 0; i < 8; i++)
                #pragma unroll
                for (int j = 0; j < 8; j++) acc[i][j] += a[i] * b[j];
        }
        __syncthreads();
    }

    #pragma unroll
    for (int i = 0; i < 8; i++) {
        int row = rowBase + ty * 8 + i;
        #pragma unroll
        for (int j = 0; j < 8; j++) {
            int col = colBase + tx * 8 + j;
            if (col < N) {
                float v = acc[i][j];
                if (mode == 1) v = res[(size_t)row * N + col] + scale[col] * v;
                else if (mode == 2) { v = fmaxf(v, 0.f); v = v * v; }
                C[(size_t)row * N + col] = v;
            }
        }
    }
}

// ---------------- causal depthwise conv (K=4) + silu on q/k/v preacts -------
__global__ void conv_silu_kernel(const float* __restrict__ wq, const float* __restrict__ wk,
                                 const float* __restrict__ wv) {
    int idx = blockIdx.x * blockDim.x + threadIdx.x;   // NTOK * 2048
    if (idx >= NTOK * 2048) return;
    int c   = idx & 2047;
    int row = idx >> 11;
    int t   = row & (T_ - 1);

    const float* w; float* outp;
    if (c < 512)        { w = wq + c * 4;          outp = g_q + (size_t)row * KDIM_ + c; }
    else if (c < 1024)  { w = wk + (c - 512) * 4;  outp = g_k + (size_t)row * KDIM_ + (c - 512); }
    else                { w = wv + (c - 1024) * 4; outp = g_v + (size_t)row * VDIM_ + (c - 1024); }

    float acc = 0.f;
    #pragma unroll
    for (int i = 0; i < 4; i++) {
        int tt = t - 3 + i;
        if (tt >= 0) acc += g_c1[(size_t)(row - 3 + i) * M1 + c] * w[i];
    }
    *outp = acc / (1.f + expf(-acc));   // silu
}

// ---------------- beta / log-decay g ----------------------------------------
__global__ void betag_kernel(const float* __restrict__ A_log, const float* __restrict__ dt_bias) {
    int idx = blockIdx.x * blockDim.x + threadIdx.x;   // NTOK * H
    if (idx >= NTOK * H_) return;
    int row = idx >> 3, h = idx & 7;
    float zb = g_c1[(size_t)row * M1 + 2048 + h];
    float za = g_c1[(size_t)row * M1 + 2056 + h];
    g_beta[idx] = 2.f / (1.f + expf(-zb));
    float z = za + dt_bias[h];
    float sp = (z > 20.f) ? z : log1pf(expf(z));
    g_g[idx] = -expf(A_log[h]) * sp;
}

// ---------------- l2-normalize q (with DK^-0.5) and k ------------------------
__global__ void l2_kernel() {
    int gwarp = (blockIdx.x * blockDim.x + threadIdx.x) >> 5;
    int lane  = threadIdx.x & 31;
    const int nvec = NTOK * H_;
    float* base; float extra;
    if (gwarp < nvec) { base = g_q + (size_t)gwarp * DK_;          extra = 0.125f; }
    else              { base = g_k + (size_t)(gwarp - nvec) * DK_; extra = 1.0f;   }
    float a = base[lane], b = base[lane + 32];
    float s = a * a + b * b;
    #pragma unroll
    for (int o = 16; o; o >>= 1) s += __shfl_xor_sync(0xffffffffu, s, o);
    float r = rsqrtf(s + 1e-6f) * extra;
    base[lane] = a * r;
    base[lane + 32] = b * r;
}

// ---------------- gated delta rule scan --------------------------------------
// block = (b,h); thread j owns v-column j; state S[64] in registers.
__global__ void __launch_bounds__(128)
delta_kernel() {
    int b = blockIdx.x >> 3, h = blockIdx.x & 7;
    int j = threadIdx.x;
    __shared__ float sq[2][64], sk[2][64];
    float S[64];
    #pragma unroll
    for (int i = 0; i < 64; i++) S[i] = 0.f;

    const size_t tok0 = (size_t)b * T_ * H_ + h;
    const float* qb = g_q + tok0 * DK_;
    const float* kb = g_k + tok0 * DK_;
    const float* vb = g_v + tok0 * DV_;
    float*       ob = g_o + tok0 * DV_;
    const float* gb = g_g + tok0;
    const float* bb = g_beta + tok0;

    if (j < 64) sq[0][j] = qb[j]; else sk[0][j - 64] = kb[j - 64];
    float vcur = vb[j];
    float gcur = gb[0], bcur = bb[0];
    __syncthreads();

    for (int t = 0; t < T_; t++) {
        int cur = t & 1, nxt = cur ^ 1;
        float vnext = 0.f, gnext = 0.f, bnext = 0.f;
        if (t + 1 < T_) {
            size_t off = (size_t)(t + 1) * H_;
            if (j < 64) sq[nxt][j] = qb[off * DK_ + j];
            else        sk[nxt][j - 64] = kb[off * DK_ + (j - 64)];
            vnext = vb[off * DV_ + j];
            gnext = gb[off];
            bnext = bb[off];
        }
        float eg = expf(gcur);
        float kv0 = 0.f, kv1 = 0.f, kv2 = 0.f, kv3 = 0.f;
        #pragma unroll
        for (int i = 0; i < 64; i += 4) {
            kv0 += S[i + 0] * sk[cur][i + 0];
            kv1 += S[i + 1] * sk[cur][i + 1];
            kv2 += S[i + 2] * sk[cur][i + 2];
            kv3 += S[i + 3] * sk[cur][i + 3];
        }
        float vres = (vcur - eg * ((kv0 + kv1) + (kv2 + kv3))) * bcur;
        float o0 = 0.f, o1 = 0.f, o2 = 0.f, o3 = 0.f;
        #pragma unroll
        for (int i = 0; i < 64; i += 4) {
            S[i + 0] = eg * S[i + 0] + sk[cur][i + 0] * vres; o0 += S[i + 0] * sq[cur][i + 0];
            S[i + 1] = eg * S[i + 1] + sk[cur][i + 1] * vres; o1 += S[i + 1] * sq[cur][i + 1];
            S[i + 2] = eg * S[i + 2] + sk[cur][i + 2] * vres; o2 += S[i + 2] * sq[cur][i + 2];
            S[i + 3] = eg * S[i + 3] + sk[cur][i + 3] * vres; o3 += S[i + 3] * sq[cur][i + 3];
        }
        ob[(size_t)t * H_ * DV_ + j] = (o0 + o1) + (o2 + o3);
        vcur = vnext; gcur = gnext; bcur = bnext;
        __syncthreads();
    }
}

// ---------------- gated RMSNorm on o: rms(o)*w*silu(gate) --------------------
__global__ void gatednorm_kernel(const float* __restrict__ o_norm_w) {
    int gvec = blockIdx.x * 8 + (threadIdx.x >> 5);   // (row, h)
    int lane = threadIdx.x & 31;
    int row = gvec >> 3, h = gvec & 7;

    const float* obase = g_o + (size_t)row * VDIM_ + h * DV_;
    float4 ov = *(const float4*)(obase + lane * 4);
    float s = ov.x * ov.x + ov.y * ov.y + ov.z * ov.z + ov.w * ov.w;
    #pragma unroll
    for (int off = 16; off; off >>= 1) s += __shfl_xor_sync(0xffffffffu, s, off);
    float scale = rsqrtf(s * (1.0f / (float)DV_) + 1e-5f);

    const float* gptr = g_c1 + (size_t)row * M1 + 2064 + h * DV_ + lane * 4;
    float4 gv = *(const float4*)gptr;
    float4 wv = *(const float4*)(o_norm_w + lane * 4);
    float4 out;
    out.x = ov.x * scale * wv.x * (gv.x / (1.f + expf(-gv.x)));
    out.y = ov.y * scale * wv.y * (gv.y / (1.f + expf(-gv.y)));
    out.z = ov.z * scale * wv.z * (gv.z / (1.f + expf(-gv.z)));
    out.w = ov.w * scale * wv.w * (gv.w / (1.f + expf(-gv.w)));
    *(float4*)(g_og + (size_t)row * VDIM_ + h * DV_ + lane * 4) = out;
}

// ---------------- launch ------------------------------------------------------
static inline int cdiv(int a, int b) { return (a + b - 1) / b; }

extern "C" void kernel_launch(void* const* d_in, const int* in_sizes, int n_in,
                              void* d_out, int out_size) {
    const float* x       = (const float*)d_in[0];
    const float* Wq      = (const float*)d_in[1];
    const float* Wk      = (const float*)d_in[2];
    const float* Wv      = (const float*)d_in[3];
    const float* Wb      = (const float*)d_in[4];
    const float* Wa      = (const float*)d_in[5];
    const float* Wg      = (const float*)d_in[6];
    const float* Wo      = (const float*)d_in[7];
    const float* conv_q  = (const float*)d_in[8];
    const float* conv_k  = (const float*)d_in[9];
    const float* conv_v  = (const float*)d_in[10];
    const float* A_log   = (const float*)d_in[11];
    const float* dt_bias = (const float*)d_in[12];
    const float* o_norm_w= (const float*)d_in[13];
    const float* W_fc    = (const float*)d_in[14];
    const float* W_proj  = (const float*)d_in[15];
    const float* gdn_scale = (const float*)d_in[16];
    const float* mlp_scale = (const float*)d_in[17];
    float* out = (float*)d_out;

    // resolve device-global addresses
    float *p_h, *p_wcat, *p_c1, *p_xmid, *p_h2, *p_m2, *p_og;
    cudaGetSymbolAddress((void**)&p_h,    g_h);
    cudaGetSymbolAddress((void**)&p_wcat, g_wcat);
    cudaGetSymbolAddress((void**)&p_c1,   g_c1);
    cudaGetSymbolAddress((void**)&p_xmid, g_xmid);
    cudaGetSymbolAddress((void**)&p_h2,   g_h2);
    cudaGetSymbolAddress((void**)&p_m2,   g_m2);
    cudaGetSymbolAddress((void**)&p_og,   g_og);

    // 0) pack fused weights
    pack_wcat<<<cdiv(M1 * D_, 256), 256>>>(Wq, Wk, Wv, Wb, Wa, Wg);

    // 1) h = rmsnorm(x)
    rms_kernel<<<NTOK, D_>>>(x, p_h);

    // 2) C1 = h @ Wcat^T   (16384 x 3088)
    sgemm_kernel<<<dim3(cdiv(M1, 128), NTOK / 128), 256>>>(
        p_h, p_wcat, p_c1, M1, D_, 0, nullptr, nullptr);

    // 3) conv + silu  -> q,k,v
    conv_silu_kernel<<<cdiv(NTOK * 2048, 256), 256>>>(conv_q, conv_k, conv_v);

    // 4) beta, g
    betag_kernel<<<cdiv(NTOK * H_, 256), 256>>>(A_log, dt_bias);

    // 5) l2 norm q (with DK^-0.5), k
    l2_kernel<<<cdiv(NTOK * H_ * 2 * 32, 256), 256>>>();

    // 6) gated delta rule scan
    delta_kernel<<<B_ * H_, 128>>>();

    // 7) gated RMSNorm(o) * silu(gate)
    gatednorm_kernel<<<NTOK * H_ / 8, 256>>>(o_norm_w);

    // 8) x_mid = x + gdn_scale * (og @ Wo^T)
    sgemm_kernel<<<dim3(cdiv(D_, 128), NTOK / 128), 256>>>(
        p_og, Wo, p_xmid, D_, VDIM_, 1, x, gdn_scale);

    // 9) h2 = rmsnorm(x_mid)
    rms_kernel<<<NTOK, D_>>>(p_xmid, p_h2);

    // 10) m2 = relu(h2 @ W_fc^T)^2
    sgemm_kernel<<<dim3(cdiv(HID_, 128), NTOK / 128), 256>>>(
        p_h2, W_fc, p_m2, HID_, D_, 2, nullptr, nullptr);

    // 11) out = x_mid + mlp_scale * (m2 @ W_proj^T)
    sgemm_kernel<<<dim3(cdiv(D_, 128), NTOK / 128), 256>>>(
        p_m2, W_proj, out, D_, HID_, 1, p_xmid, mlp_scale);
}

// round 3
// speedup vs baseline: 1.9022x; 1.9022x over previous
#include <cuda_runtime.h>
#include <cstdint>

#define B_  8
#define T_  2048
#define D_  544
#define H_  8
#define DK_ 64
#define DV_ 128
#define KDIM_ 512
#define VDIM_ 1024
#define HID_ 1632
#define NTOK (B_*T_)          // 16384
#define M1   3088             // 512+512+1024+8+8+1024 fused out dims

// ---------------- scratch (device globals; no runtime alloc allowed) --------
static __device__ float g_h   [NTOK * D_];
static __device__ float g_wcat[M1 * D_];
static __device__ float g_c1  [(size_t)NTOK * M1];
static __device__ float g_q   [(size_t)NTOK * KDIM_];
static __device__ float g_k   [(size_t)NTOK * KDIM_];
static __device__ float g_v   [(size_t)NTOK * VDIM_];
static __device__ float g_beta[NTOK * H_];
static __device__ float g_g   [NTOK * H_];
static __device__ float g_o   [(size_t)NTOK * VDIM_];
static __device__ float g_og  [(size_t)NTOK * VDIM_];
static __device__ float g_xmid[NTOK * D_];
static __device__ float g_h2  [NTOK * D_];
static __device__ float g_m2  [(size_t)NTOK * HID_];

__device__ __forceinline__ float ftf32(float x) {
    uint32_t u;
    asm("cvt.rna.tf32.f32 %0, %1;" : "=r"(u) : "f"(x));
    return __uint_as_float(u);
}

__device__ __forceinline__ void mma_tf32(float* c, const float* a, const float* b) {
    asm volatile(
        "mma.sync.aligned.m16n8k8.row.col.f32.tf32.tf32.f32 "
        "{%0,%1,%2,%3}, {%4,%5,%6,%7}, {%8,%9}, {%0,%1,%2,%3};"
        : "+f"(c[0]), "+f"(c[1]), "+f"(c[2]), "+f"(c[3])
        : "r"(__float_as_uint(a[0])), "r"(__float_as_uint(a[1])),
          "r"(__float_as_uint(a[2])), "r"(__float_as_uint(a[3])),
          "r"(__float_as_uint(b[0])), "r"(__float_as_uint(b[1])));
}

// ============== mma.sync tf32 GEMM: C[M,N] = A[M,K] @ B[N,K]^T ===============
// 128x128 block tile, BK=16, 256 threads = 8 warps (2 warpM x 4 warpN),
// warp tile 64x32 = 4x4 m16n8k8 fragments. Double-buffered SMEM, stride 20.
// modes: 0: C=acc; 1: C=res+scale[col]*acc; 2: C=relu(acc)^2
#define SSTRIDE 20
__global__ void __launch_bounds__(256)
tmma_gemm(const float* __restrict__ A, const float* __restrict__ B,
          float* __restrict__ C, int N, int K, int mode,
          const float* __restrict__ res, const float* __restrict__ scale) {
    __shared__ float sA[2][128 * SSTRIDE];
    __shared__ float sB[2][128 * SSTRIDE];

    const int tid  = threadIdx.x;
    const int wid  = tid >> 5, lane = tid & 31;
    const int warpM = wid & 1;          // 0..1  -> 64 rows each
    const int warpN = wid >> 1;         // 0..3  -> 32 cols each
    const int rowBase = blockIdx.y * 128;
    const int colBase = blockIdx.x * 128;

    const int r0 = lane >> 2;           // 0..7
    const int c0 = lane & 3;            // 0..3

    float acc[4][4][4];
    #pragma unroll
    for (int mt = 0; mt < 4; mt++)
        #pragma unroll
        for (int nt = 0; nt < 4; nt++)
            #pragma unroll
            for (int i = 0; i < 4; i++) acc[mt][nt][i] = 0.f;

    const int NK = K >> 4;              // k-tiles of 16

    // gmem load mapping: float4 f = tid + i*256 -> row f>>2, col (f&3)*4
    const int lr0 = tid >> 2, lc0 = (tid & 3) * 4;
    const int lr1 = (tid + 256) >> 2, lc1 = ((tid + 256) & 3) * 4;

    // ---- prologue: stage 0 ----
    {
        float4 a0 = *(const float4*)(A + (size_t)(rowBase + lr0) * K + lc0);
        float4 a1 = *(const float4*)(A + (size_t)(rowBase + lr1) * K + lc1);
        int bn0 = colBase + lr0, bn1 = colBase + lr1;
        float4 b0 = (bn0 < N) ? *(const float4*)(B + (size_t)bn0 * K + lc0)
                              : make_float4(0.f,0.f,0.f,0.f);
        float4 b1 = (bn1 < N) ? *(const float4*)(B + (size_t)bn1 * K + lc1)
                              : make_float4(0.f,0.f,0.f,0.f);
        float* pa0 = &sA[0][lr0 * SSTRIDE + lc0];
        pa0[0]=ftf32(a0.x); pa0[1]=ftf32(a0.y); pa0[2]=ftf32(a0.z); pa0[3]=ftf32(a0.w);
        float* pa1 = &sA[0][lr1 * SSTRIDE + lc1];
        pa1[0]=ftf32(a1.x); pa1[1]=ftf32(a1.y); pa1[2]=ftf32(a1.z); pa1[3]=ftf32(a1.w);
        float* pb0 = &sB[0][lr0 * SSTRIDE + lc0];
        pb0[0]=ftf32(b0.x); pb0[1]=ftf32(b0.y); pb0[2]=ftf32(b0.z); pb0[3]=ftf32(b0.w);
        float* pb1 = &sB[0][lr1 * SSTRIDE + lc1];
        pb1[0]=ftf32(b1.x); pb1[1]=ftf32(b1.y); pb1[2]=ftf32(b1.z); pb1[3]=ftf32(b1.w);
    }
    __syncthreads();

    for (int kt = 0; kt < NK; kt++) {
        const int cur = kt & 1, nxt = cur ^ 1;
        const bool have_next = (kt + 1 < NK);
        float4 ra0, ra1, rb0, rb1;
        if (have_next) {
            int kb = (kt + 1) * 16;
            ra0 = *(const float4*)(A + (size_t)(rowBase + lr0) * K + kb + lc0);
            ra1 = *(const float4*)(A + (size_t)(rowBase + lr1) * K + kb + lc1);
            int bn0 = colBase + lr0, bn1 = colBase + lr1;
            rb0 = (bn0 < N) ? *(const float4*)(B + (size_t)bn0 * K + kb + lc0)
                            : make_float4(0.f,0.f,0.f,0.f);
            rb1 = (bn1 < N) ? *(const float4*)(B + (size_t)bn1 * K + kb + lc1)
                            : make_float4(0.f,0.f,0.f,0.f);
        }

        // ---- compute on stage cur: 2 k-steps of 8 ----
        #pragma unroll
        for (int ks = 0; ks < 2; ks++) {
            const int kc = ks * 8 + c0;
            float af[4][4], bf[4][2];
            #pragma unroll
            for (int mt = 0; mt < 4; mt++) {
                int row = warpM * 64 + mt * 16 + r0;
                af[mt][0] = sA[cur][row * SSTRIDE + kc];
                af[mt][1] = sA[cur][(row + 8) * SSTRIDE + kc];
                af[mt][2] = sA[cur][row * SSTRIDE + kc + 4];
                af[mt][3] = sA[cur][(row + 8) * SSTRIDE + kc + 4];
            }
            #pragma unroll
            for (int nt = 0; nt < 4; nt++) {
                int nr = warpN * 32 + nt * 8 + r0;
                bf[nt][0] = sB[cur][nr * SSTRIDE + kc];
                bf[nt][1] = sB[cur][nr * SSTRIDE + kc + 4];
            }
            #pragma unroll
            for (int mt = 0; mt < 4; mt++)
                #pragma unroll
                for (int nt = 0; nt < 4; nt++)
                    mma_tf32(acc[mt][nt], af[mt], bf[nt]);
        }

        if (have_next) {
            float* pa0 = &sA[nxt][lr0 * SSTRIDE + lc0];
            pa0[0]=ftf32(ra0.x); pa0[1]=ftf32(ra0.y); pa0[2]=ftf32(ra0.z); pa0[3]=ftf32(ra0.w);
            float* pa1 = &sA[nxt][lr1 * SSTRIDE + lc1];
            pa1[0]=ftf32(ra1.x); pa1[1]=ftf32(ra1.y); pa1[2]=ftf32(ra1.z); pa1[3]=ftf32(ra1.w);
            float* pb0 = &sB[nxt][lr0 * SSTRIDE + lc0];
            pb0[0]=ftf32(rb0.x); pb0[1]=ftf32(rb0.y); pb0[2]=ftf32(rb0.z); pb0[3]=ftf32(rb0.w);
            float* pb1 = &sB[nxt][lr1 * SSTRIDE + lc1];
            pb1[0]=ftf32(rb1.x); pb1[1]=ftf32(rb1.y); pb1[2]=ftf32(rb1.z); pb1[3]=ftf32(rb1.w);
        }
        __syncthreads();
    }

    // ---- epilogue ----
    #pragma unroll
    for (int mt = 0; mt < 4; mt++) {
        #pragma unroll
        for (int half = 0; half < 2; half++) {
            int row = rowBase + warpM * 64 + mt * 16 + r0 + half * 8;
            #pragma unroll
            for (int nt = 0; nt < 4; nt++) {
                int col = colBase + warpN * 32 + nt * 8 + 2 * c0;
                if (col < N) {
                    float v0 = acc[mt][nt][half * 2 + 0];
                    float v1 = acc[mt][nt][half * 2 + 1];
                    if (mode == 1) {
                        const float* rp = res + (size_t)row * N + col;
                        v0 = rp[0] + scale[col] * v0;
                        v1 = rp[1] + scale[col + 1] * v1;
                    } else if (mode == 2) {
                        v0 = fmaxf(v0, 0.f); v0 = v0 * v0;
                        v1 = fmaxf(v1, 0.f); v1 = v1 * v1;
                    }
                    *(float2*)(C + (size_t)row * N + col) = make_float2(v0, v1);
                }
            }
        }
    }
}

// ---------------- pack fused weight matrix [3088 x 544] ---------------------
__global__ void pack_wcat(const float* __restrict__ Wq, const float* __restrict__ Wk,
                          const float* __restrict__ Wv, const float* __restrict__ Wb,
                          const float* __restrict__ Wa, const float* __restrict__ Wg) {
    int idx = blockIdx.x * blockDim.x + threadIdx.x;
    if (idx >= M1 * D_) return;
    int row = idx / D_, col = idx % D_;
    float v;
    if      (row < 512)  v = Wq[row * D_ + col];
    else if (row < 1024) v = Wk[(row - 512) * D_ + col];
    else if (row < 2048) v = Wv[(row - 1024) * D_ + col];
    else if (row < 2056) v = Wb[(row - 2048) * D_ + col];
    else if (row < 2064) v = Wa[(row - 2056) * D_ + col];
    else                 v = Wg[(row - 2064) * D_ + col];
    g_wcat[idx] = v;
}

// ---------------- parameter-free RMSNorm over D=544 -------------------------
__global__ void rms_kernel(const float* __restrict__ x, float* __restrict__ y) {
    int row = blockIdx.x;
    int tid = threadIdx.x;          // blockDim = 544 (17 warps)
    float v = x[(size_t)row * D_ + tid];
    float s = v * v;
    #pragma unroll
    for (int o = 16; o; o >>= 1) s += __shfl_xor_sync(0xffffffffu, s, o);
    __shared__ float ws[17];
    if ((tid & 31) == 0) ws[tid >> 5] = s;
    __syncthreads();
    if (tid < 32) {
        float t = (tid < 17) ? ws[tid] : 0.f;
        #pragma unroll
        for (int o = 16; o; o >>= 1) t += __shfl_xor_sync(0xffffffffu, t, o);
        if (tid == 0) ws[0] = t;
    }
    __syncthreads();
    float scale = rsqrtf(ws[0] * (1.0f / (float)D_) + 1e-6f);
    y[(size_t)row * D_ + tid] = v * scale;
}

// ---------------- causal depthwise conv (K=4) + silu on q/k/v preacts -------
__global__ void conv_silu_kernel(const float* __restrict__ wq, const float* __restrict__ wk,
                                 const float* __restrict__ wv) {
    int idx = blockIdx.x * blockDim.x + threadIdx.x;   // NTOK * 2048
    if (idx >= NTOK * 2048) return;
    int c   = idx & 2047;
    int row = idx >> 11;
    int t   = row & (T_ - 1);

    const float* w; float* outp;
    if (c < 512)        { w = wq + c * 4;          outp = g_q + (size_t)row * KDIM_ + c; }
    else if (c < 1024)  { w = wk + (c - 512) * 4;  outp = g_k + (size_t)row * KDIM_ + (c - 512); }
    else                { w = wv + (c - 1024) * 4; outp = g_v + (size_t)row * VDIM_ + (c - 1024); }

    float acc = 0.f;
    #pragma unroll
    for (int i = 0; i < 4; i++) {
        int tt = t - 3 + i;
        if (tt >= 0) acc += g_c1[(size_t)(row - 3 + i) * M1 + c] * w[i];
    }
    *outp = acc / (1.f + expf(-acc));   // silu
}

// ---------------- beta / log-decay g ----------------------------------------
__global__ void betag_kernel(const float* __restrict__ A_log, const float* __restrict__ dt_bias) {
    int idx = blockIdx.x * blockDim.x + threadIdx.x;   // NTOK * H
    if (idx >= NTOK * H_) return;
    int row = idx >> 3, h = idx & 7;
    float zb = g_c1[(size_t)row * M1 + 2048 + h];
    float za = g_c1[(size_t)row * M1 + 2056 + h];
    g_beta[idx] = 2.f / (1.f + expf(-zb));
    float z = za + dt_bias[h];
    float sp = (z > 20.f) ? z : log1pf(expf(z));
    g_g[idx] = -expf(A_log[h]) * sp;
}

// ---------------- l2-normalize q (with DK^-0.5) and k ------------------------
__global__ void l2_kernel() {
    int gwarp = (blockIdx.x * blockDim.x + threadIdx.x) >> 5;
    int lane  = threadIdx.x & 31;
    const int nvec = NTOK * H_;
    float* base; float extra;
    if (gwarp < nvec) { base = g_q + (size_t)gwarp * DK_;          extra = 0.125f; }
    else              { base = g_k + (size_t)(gwarp - nvec) * DK_; extra = 1.0f;   }
    float a = base[lane], b = base[lane + 32];
    float s = a * a + b * b;
    #pragma unroll
    for (int o = 16; o; o >>= 1) s += __shfl_xor_sync(0xffffffffu, s, o);
    float r = rsqrtf(s + 1e-6f) * extra;
    base[lane] = a * r;
    base[lane + 32] = b * r;
}

// ---------------- gated delta rule scan --------------------------------------
// block = (b,h,vhalf): 128 CTAs. 128 threads: thread = jloc*2 + kh.
// Thread owns S[kh*32 : kh*32+32][vhalf*64 + jloc]; pairs combine via shfl.
__global__ void __launch_bounds__(128)
delta_kernel() {
    int bh = blockIdx.x >> 1;
    int vh = blockIdx.x & 1;
    int b = bh >> 3, h = bh & 7;
    int tid = threadIdx.x;
    int jloc = tid >> 1;
    int kh   = tid & 1;
    int j = vh * 64 + jloc;
    const int kofs = kh * 32;

    __shared__ float sq[2][64], sk[2][64];
    float S[32];
    #pragma unroll
    for (int i = 0; i < 32; i++) S[i] = 0.f;

    const size_t tok0 = (size_t)b * T_ * H_ + h;
    const float* qb = g_q + tok0 * DK_;
    const float* kb = g_k + tok0 * DK_;
    const float* vb = g_v + tok0 * DV_;
    float*       ob = g_o + tok0 * DV_;
    const float* gb = g_g + tok0;
    const float* bbp = g_beta + tok0;

    if (tid < 64) sq[0][tid] = qb[tid]; else sk[0][tid - 64] = kb[tid - 64];
    float vcur = vb[j];
    float gcur = gb[0], bcur = bbp[0];
    __syncthreads();

    for (int t = 0; t < T_; t++) {
        int cur = t & 1, nxt = cur ^ 1;
        float vnext = 0.f, gnext = 0.f, bnext = 0.f;
        if (t + 1 < T_) {
            size_t off = (size_t)(t + 1) * H_;
            if (tid < 64) sq[nxt][tid] = qb[off * DK_ + tid];
            else          sk[nxt][tid - 64] = kb[off * DK_ + (tid - 64)];
            vnext = vb[off * DV_ + j];
            gnext = gb[off];
            bnext = bbp[off];
        }
        float eg = expf(gcur);

        float kk[32];
        #pragma unroll
        for (int i = 0; i < 32; i += 4) {
            float4 t4 = *(const float4*)&sk[cur][kofs + i];
            kk[i] = t4.x; kk[i+1] = t4.y; kk[i+2] = t4.z; kk[i+3] = t4.w;
        }
        float kv0 = 0.f, kv1 = 0.f, kv2 = 0.f, kv3 = 0.f;
        #pragma unroll
        for (int i = 0; i < 32; i += 4) {
            kv0 += S[i + 0] * kk[i + 0];
            kv1 += S[i + 1] * kk[i + 1];
            kv2 += S[i + 2] * kk[i + 2];
            kv3 += S[i + 3] * kk[i + 3];
        }
        float kv = (kv0 + kv1) + (kv2 + kv3);
        kv += __shfl_xor_sync(0xffffffffu, kv, 1);
        float vres = (vcur - eg * kv) * bcur;

        float o0 = 0.f, o1 = 0.f, o2 = 0.f, o3 = 0.f;
        #pragma unroll
        for (int i = 0; i < 32; i += 4) {
            float4 q4 = *(const float4*)&sq[cur][kofs + i];
            S[i + 0] = eg * S[i + 0] + kk[i + 0] * vres; o0 += S[i + 0] * q4.x;
            S[i + 1] = eg * S[i + 1] + kk[i + 1] * vres; o1 += S[i + 1] * q4.y;
            S[i + 2] = eg * S[i + 2] + kk[i + 2] * vres; o2 += S[i + 2] * q4.z;
            S[i + 3] = eg * S[i + 3] + kk[i + 3] * vres; o3 += S[i + 3] * q4.w;
        }
        float o = (o0 + o1) + (o2 + o3);
        o += __shfl_xor_sync(0xffffffffu, o, 1);
        if (kh == 0) ob[(size_t)t * H_ * DV_ + j] = o;

        vcur = vnext; gcur = gnext; bcur = bnext;
        __syncthreads();
    }
}

// ---------------- gated RMSNorm on o: rms(o)*w*silu(gate) --------------------
__global__ void gatednorm_kernel(const float* __restrict__ o_norm_w) {
    int gvec = blockIdx.x * 8 + (threadIdx.x >> 5);   // (row, h)
    int lane = threadIdx.x & 31;
    int row = gvec >> 3, h = gvec & 7;

    const float* obase = g_o + (size_t)row * VDIM_ + h * DV_;
    float4 ov = *(const float4*)(obase + lane * 4);
    float s = ov.x * ov.x + ov.y * ov.y + ov.z * ov.z + ov.w * ov.w;
    #pragma unroll
    for (int off = 16; off; off >>= 1) s += __shfl_xor_sync(0xffffffffu, s, off);
    float scale = rsqrtf(s * (1.0f / (float)DV_) + 1e-5f);

    const float* gptr = g_c1 + (size_t)row * M1 + 2064 + h * DV_ + lane * 4;
    float4 gv = *(const float4*)gptr;
    float4 wv = *(const float4*)(o_norm_w + lane * 4);
    float4 out;
    out.x = ov.x * scale * wv.x * (gv.x / (1.f + expf(-gv.x)));
    out.y = ov.y * scale * wv.y * (gv.y / (1.f + expf(-gv.y)));
    out.z = ov.z * scale * wv.z * (gv.z / (1.f + expf(-gv.z)));
    out.w = ov.w * scale * wv.w * (gv.w / (1.f + expf(-gv.w)));
    *(float4*)(g_og + (size_t)row * VDIM_ + h * DV_ + lane * 4) = out;
}

// ---------------- launch ------------------------------------------------------
static inline int cdiv(int a, int b) { return (a + b - 1) / b; }

extern "C" void kernel_launch(void* const* d_in, const int* in_sizes, int n_in,
                              void* d_out, int out_size) {
    const float* x       = (const float*)d_in[0];
    const float* Wq      = (const float*)d_in[1];
    const float* Wk      = (const float*)d_in[2];
    const float* Wv      = (const float*)d_in[3];
    const float* Wb      = (const float*)d_in[4];
    const float* Wa      = (const float*)d_in[5];
    const float* Wg      = (const float*)d_in[6];
    const float* Wo      = (const float*)d_in[7];
    const float* conv_q  = (const float*)d_in[8];
    const float* conv_k  = (const float*)d_in[9];
    const float* conv_v  = (const float*)d_in[10];
    const float* A_log   = (const float*)d_in[11];
    const float* dt_bias = (const float*)d_in[12];
    const float* o_norm_w= (const float*)d_in[13];
    const float* W_fc    = (const float*)d_in[14];
    const float* W_proj  = (const float*)d_in[15];
    const float* gdn_scale = (const float*)d_in[16];
    const float* mlp_scale = (const float*)d_in[17];
    float* out = (float*)d_out;

    float *p_h, *p_wcat, *p_c1, *p_xmid, *p_h2, *p_m2, *p_og;
    cudaGetSymbolAddress((void**)&p_h,    g_h);
    cudaGetSymbolAddress((void**)&p_wcat, g_wcat);
    cudaGetSymbolAddress((void**)&p_c1,   g_c1);
    cudaGetSymbolAddress((void**)&p_xmid, g_xmid);
    cudaGetSymbolAddress((void**)&p_h2,   g_h2);
    cudaGetSymbolAddress((void**)&p_m2,   g_m2);
    cudaGetSymbolAddress((void**)&p_og,   g_og);

    // 0) pack fused weights
    pack_wcat<<<cdiv(M1 * D_, 256), 256>>>(Wq, Wk, Wv, Wb, Wa, Wg);

    // 1) h = rmsnorm(x)
    rms_kernel<<<NTOK, D_>>>(x, p_h);

    // 2) C1 = h @ Wcat^T   (16384 x 3088), K=544
    tmma_gemm<<<dim3(cdiv(M1, 128), NTOK / 128), 256>>>(
        p_h, p_wcat, p_c1, M1, D_, 0, nullptr, nullptr);

    // 3) conv + silu  -> q,k,v
    conv_silu_kernel<<<cdiv(NTOK * 2048, 256), 256>>>(conv_q, conv_k, conv_v);

    // 4) beta, g
    betag_kernel<<<cdiv(NTOK * H_, 256), 256>>>(A_log, dt_bias);

    // 5) l2 norm q (with DK^-0.5), k
    l2_kernel<<<cdiv(NTOK * H_ * 2 * 32, 256), 256>>>();

    // 6) gated delta rule scan
    delta_kernel<<<B_ * H_ * 2, 128>>>();

    // 7) gated RMSNorm(o) * silu(gate)
    gatednorm_kernel<<<NTOK * H_ / 8, 256>>>(o_norm_w);

    // 8) x_mid = x + gdn_scale * (og @ Wo^T), K=1024
    tmma_gemm<<<dim3(cdiv(D_, 128), NTOK / 128), 256>>>(
        p_og, Wo, p_xmid, D_, VDIM_, 1, x, gdn_scale);

    // 9) h2 = rmsnorm(x_mid)
    rms_kernel<<<NTOK, D_>>>(p_xmid, p_h2);

    // 10) m2 = relu(h2 @ W_fc^T)^2, K=544
    tmma_gemm<<<dim3(cdiv(HID_, 128), NTOK / 128), 256>>>(
        p_h2, W_fc, p_m2, HID_, D_, 2, nullptr, nullptr);

    // 11) out = x_mid + mlp_scale * (m2 @ W_proj^T), K=1632
    tmma_gemm<<<dim3(cdiv(D_, 128), NTOK / 128), 256>>>(
        p_m2, W_proj, out, D_, HID_, 1, p_xmid, mlp_scale);
}

// round 4
// speedup vs baseline: 2.6757x; 1.4066x over previous
#include <cuda_runtime.h>
#include <cstdint>

#define B_  8
#define T_  2048
#define D_  544
#define H_  8
#define DK_ 64
#define DV_ 128
#define KDIM_ 512
#define VDIM_ 1024
#define HID_ 1632
#define NTOK (B_*T_)          // 16384
#define M1   3088             // 512+512+1024+8+8+1024 fused out dims

// ---------------- scratch (device globals; no runtime alloc allowed) --------
static __device__ float g_h   [NTOK * D_];
static __device__ float g_wcat[M1 * D_];
static __device__ float g_c1  [(size_t)NTOK * M1];
static __device__ float g_q   [(size_t)NTOK * KDIM_];
static __device__ float g_k   [(size_t)NTOK * KDIM_];
static __device__ float g_v   [(size_t)NTOK * VDIM_];
static __device__ float g_beta[NTOK * H_];
static __device__ float g_g   [NTOK * H_];
static __device__ float g_o   [(size_t)NTOK * VDIM_];
static __device__ float g_og  [(size_t)NTOK * VDIM_];
static __device__ float g_xmid[NTOK * D_];
static __device__ float g_h2  [NTOK * D_];
static __device__ float g_m2  [(size_t)NTOK * HID_];

// ============================ helpers ========================================
__device__ __forceinline__ uint32_t smem_u32(const void* p) {
    uint32_t a;
    asm("{ .reg .u64 t; cvta.to.shared.u64 t, %1; cvt.u32.u64 %0, t; }" : "=r"(a) : "l"(p));
    return a;
}
// pack (lo, hi) floats into bf16x2 (lo at lower address / lower 16 bits)
__device__ __forceinline__ uint32_t f2bf2(float lo, float hi) {
    uint32_t r;
    asm("cvt.rn.bf16x2.f32 %0, %1, %2;" : "=r"(r) : "f"(hi), "f"(lo));
    return r;
}
__device__ __forceinline__ void ldsm_x4(uint32_t* r, uint32_t addr) {
    asm volatile("ldmatrix.sync.aligned.m8n8.x4.shared.b16 {%0,%1,%2,%3}, [%4];"
        : "=r"(r[0]), "=r"(r[1]), "=r"(r[2]), "=r"(r[3]) : "r"(addr));
}
__device__ __forceinline__ void ldsm_x2(uint32_t* r, uint32_t addr) {
    asm volatile("ldmatrix.sync.aligned.m8n8.x2.shared.b16 {%0,%1}, [%2];"
        : "=r"(r[0]), "=r"(r[1]) : "r"(addr));
}
__device__ __forceinline__ void mma_bf16(float* c, const uint32_t* a, const uint32_t* b) {
    asm volatile(
        "mma.sync.aligned.m16n8k16.row.col.f32.bf16.bf16.f32 "
        "{%0,%1,%2,%3}, {%4,%5,%6,%7}, {%8,%9}, {%0,%1,%2,%3};"
        : "+f"(c[0]), "+f"(c[1]), "+f"(c[2]), "+f"(c[3])
        : "r"(a[0]), "r"(a[1]), "r"(a[2]), "r"(a[3]), "r"(b[0]), "r"(b[1]));
}

// ============== mma.sync bf16 GEMM: C[M,N] = A[M,K] @ B[N,K]^T ===============
// 128x128 block tile, BK=32, 256 threads = 8 warps (2 warpM x 4 warpN),
// warp tile 64x32 = 4x4 m16n8k16 fragments. fp32 gmem -> bf16 smem convert.
// Double-buffered SMEM, bf16 row stride 40 (80B): ldmatrix conflict-free.
// modes: 0: C=acc; 1: C=res+scale[col]*acc; 2: C=relu(acc)^2
#define SST 40
__global__ void __launch_bounds__(256)
tmma_gemm(const float* __restrict__ A, const float* __restrict__ B,
          float* __restrict__ C, int N, int K, int mode,
          const float* __restrict__ res, const float* __restrict__ scale) {
    __shared__ __align__(16) uint16_t sA[2][128 * SST];
    __shared__ __align__(16) uint16_t sB[2][128 * SST];

    const int tid  = threadIdx.x;
    const int wid  = tid >> 5, lane = tid & 31;
    const int warpM = wid & 1;          // 0..1 -> 64 rows
    const int warpN = wid >> 1;         // 0..3 -> 32 cols
    const int rowBase = blockIdx.y * 128;
    const int colBase = blockIdx.x * 128;

    const int r0 = lane >> 2;           // 0..7
    const int c0 = lane & 3;            // 0..3

    float acc[4][4][4];
    #pragma unroll
    for (int mt = 0; mt < 4; mt++)
        #pragma unroll
        for (int nt = 0; nt < 4; nt++)
            #pragma unroll
            for (int i = 0; i < 4; i++) acc[mt][nt][i] = 0.f;

    const int NK = K >> 5;              // k-tiles of 32

    // gmem->smem mapping: 4 iterations, idx = tid + it*256; row idx>>3, colgrp idx&7
    const int lr = tid >> 3;            // base row (0..31), +32 per it
    const int lc = (tid & 7) * 4;       // col within 32

    // ldmatrix source addresses (byte offsets within one stage)
    const uint32_t aBase = smem_u32(&sA[0][0]);
    const uint32_t bBase = smem_u32(&sB[0][0]);
    const uint32_t stageBytes = 128 * SST * 2;
    // A: row = warpM*64 + mt*16 + (lane&15), coloff = (lane>>4)*8
    const uint32_t aRowOff = (uint32_t)((warpM * 64 + (lane & 15)) * SST + (lane >> 4) * 8) * 2;
    // B: row = warpN*32 + nt*8 + (lane&7), coloff = ((lane>>3)&1)*8   (lanes 0-15 used)
    const uint32_t bRowOff = (uint32_t)((warpN * 32 + (lane & 7)) * SST + ((lane >> 3) & 1) * 8) * 2;

    // ---- prologue: stage 0 ----
    #pragma unroll
    for (int it = 0; it < 4; it++) {
        int r = lr + it * 32;
        float4 a4 = *(const float4*)(A + (size_t)(rowBase + r) * K + lc);
        int bn = colBase + r;
        float4 b4 = (bn < N) ? *(const float4*)(B + (size_t)bn * K + lc)
                             : make_float4(0.f, 0.f, 0.f, 0.f);
        *(uint2*)&sA[0][r * SST + lc] = make_uint2(f2bf2(a4.x, a4.y), f2bf2(a4.z, a4.w));
        *(uint2*)&sB[0][r * SST + lc] = make_uint2(f2bf2(b4.x, b4.y), f2bf2(b4.z, b4.w));
    }
    __syncthreads();

    for (int kt = 0; kt < NK; kt++) {
        const int cur = kt & 1, nxt = cur ^ 1;
        const bool have_next = (kt + 1 < NK);
        float4 ra[4], rb[4];
        if (have_next) {
            int kb = (kt + 1) * 32;
            #pragma unroll
            for (int it = 0; it < 4; it++) {
                int r = lr + it * 32;
                ra[it] = *(const float4*)(A + (size_t)(rowBase + r) * K + kb + lc);
                int bn = colBase + r;
                rb[it] = (bn < N) ? *(const float4*)(B + (size_t)bn * K + kb + lc)
                                  : make_float4(0.f, 0.f, 0.f, 0.f);
            }
        }

        // ---- compute on stage cur: 2 k-steps of 16 ----
        const uint32_t aS = aBase + cur * stageBytes + aRowOff;
        const uint32_t bS = bBase + cur * stageBytes + bRowOff;
        #pragma unroll
        for (int ks = 0; ks < 2; ks++) {
            uint32_t af[4][4], bf[4][2];
            #pragma unroll
            for (int mt = 0; mt < 4; mt++)
                ldsm_x4(af[mt], aS + (uint32_t)(mt * 16 * SST) * 2 + ks * 32);
            #pragma unroll
            for (int nt = 0; nt < 4; nt++)
                ldsm_x2(bf[nt], bS + (uint32_t)(nt * 8 * SST) * 2 + ks * 32);
            #pragma unroll
            for (int mt = 0; mt < 4; mt++)
                #pragma unroll
                for (int nt = 0; nt < 4; nt++)
                    mma_bf16(acc[mt][nt], af[mt], bf[nt]);
        }

        if (have_next) {
            #pragma unroll
            for (int it = 0; it < 4; it++) {
                int r = lr + it * 32;
                *(uint2*)&sA[nxt][r * SST + lc] =
                    make_uint2(f2bf2(ra[it].x, ra[it].y), f2bf2(ra[it].z, ra[it].w));
                *(uint2*)&sB[nxt][r * SST + lc] =
                    make_uint2(f2bf2(rb[it].x, rb[it].y), f2bf2(rb[it].z, rb[it].w));
            }
        }
        __syncthreads();
    }

    // ---- epilogue ----
    #pragma unroll
    for (int mt = 0; mt < 4; mt++) {
        #pragma unroll
        for (int half = 0; half < 2; half++) {
            int row = rowBase + warpM * 64 + mt * 16 + r0 + half * 8;
            #pragma unroll
            for (int nt = 0; nt < 4; nt++) {
                int col = colBase + warpN * 32 + nt * 8 + 2 * c0;
                if (col < N) {
                    float v0 = acc[mt][nt][half * 2 + 0];
                    float v1 = acc[mt][nt][half * 2 + 1];
                    if (mode == 1) {
                        const float* rp = res + (size_t)row * N + col;
                        v0 = rp[0] + scale[col] * v0;
                        v1 = rp[1] + scale[col + 1] * v1;
                    } else if (mode == 2) {
                        v0 = fmaxf(v0, 0.f); v0 = v0 * v0;
                        v1 = fmaxf(v1, 0.f); v1 = v1 * v1;
                    }
                    *(float2*)(C + (size_t)row * N + col) = make_float2(v0, v1);
                }
            }
        }
    }
}

// ---------------- pack fused weight matrix [3088 x 544] ---------------------
__global__ void pack_wcat(const float* __restrict__ Wq, const float* __restrict__ Wk,
                          const float* __restrict__ Wv, const float* __restrict__ Wb,
                          const float* __restrict__ Wa, const float* __restrict__ Wg) {
    int idx = blockIdx.x * blockDim.x + threadIdx.x;
    if (idx >= M1 * D_) return;
    int row = idx / D_, col = idx % D_;
    float v;
    if      (row < 512)  v = Wq[row * D_ + col];
    else if (row < 1024) v = Wk[(row - 512) * D_ + col];
    else if (row < 2048) v = Wv[(row - 1024) * D_ + col];
    else if (row < 2056) v = Wb[(row - 2048) * D_ + col];
    else if (row < 2064) v = Wa[(row - 2056) * D_ + col];
    else                 v = Wg[(row - 2064) * D_ + col];
    g_wcat[idx] = v;
}

// ---------------- parameter-free RMSNorm over D=544 -------------------------
__global__ void rms_kernel(const float* __restrict__ x, float* __restrict__ y) {
    int row = blockIdx.x;
    int tid = threadIdx.x;          // blockDim = 544 (17 warps)
    float v = x[(size_t)row * D_ + tid];
    float s = v * v;
    #pragma unroll
    for (int o = 16; o; o >>= 1) s += __shfl_xor_sync(0xffffffffu, s, o);
    __shared__ float ws[17];
    if ((tid & 31) == 0) ws[tid >> 5] = s;
    __syncthreads();
    if (tid < 32) {
        float t = (tid < 17) ? ws[tid] : 0.f;
        #pragma unroll
        for (int o = 16; o; o >>= 1) t += __shfl_xor_sync(0xffffffffu, t, o);
        if (tid == 0) ws[0] = t;
    }
    __syncthreads();
    float scale = rsqrtf(ws[0] * (1.0f / (float)D_) + 1e-6f);
    y[(size_t)row * D_ + tid] = v * scale;
}

// ---------------- causal depthwise conv (K=4) + silu on q/k/v preacts -------
__global__ void conv_silu_kernel(const float* __restrict__ wq, const float* __restrict__ wk,
                                 const float* __restrict__ wv) {
    int idx = blockIdx.x * blockDim.x + threadIdx.x;   // NTOK * 2048
    if (idx >= NTOK * 2048) return;
    int c   = idx & 2047;
    int row = idx >> 11;
    int t   = row & (T_ - 1);

    const float* w; float* outp;
    if (c < 512)        { w = wq + c * 4;          outp = g_q + (size_t)row * KDIM_ + c; }
    else if (c < 1024)  { w = wk + (c - 512) * 4;  outp = g_k + (size_t)row * KDIM_ + (c - 512); }
    else                { w = wv + (c - 1024) * 4; outp = g_v + (size_t)row * VDIM_ + (c - 1024); }

    float acc = 0.f;
    #pragma unroll
    for (int i = 0; i < 4; i++) {
        int tt = t - 3 + i;
        if (tt >= 0) acc += g_c1[(size_t)(row - 3 + i) * M1 + c] * w[i];
    }
    *outp = acc / (1.f + expf(-acc));   // silu
}

// ---------------- beta / log-decay g ----------------------------------------
__global__ void betag_kernel(const float* __restrict__ A_log, const float* __restrict__ dt_bias) {
    int idx = blockIdx.x * blockDim.x + threadIdx.x;   // NTOK * H
    if (idx >= NTOK * H_) return;
    int row = idx >> 3, h = idx & 7;
    float zb = g_c1[(size_t)row * M1 + 2048 + h];
    float za = g_c1[(size_t)row * M1 + 2056 + h];
    g_beta[idx] = 2.f / (1.f + expf(-zb));
    float z = za + dt_bias[h];
    float sp = (z > 20.f) ? z : log1pf(expf(z));
    g_g[idx] = -expf(A_log[h]) * sp;
}

// ---------------- l2-normalize q (with DK^-0.5) and k ------------------------
__global__ void l2_kernel() {
    int gwarp = (blockIdx.x * blockDim.x + threadIdx.x) >> 5;
    int lane  = threadIdx.x & 31;
    const int nvec = NTOK * H_;
    float* base; float extra;
    if (gwarp < nvec) { base = g_q + (size_t)gwarp * DK_;          extra = 0.125f; }
    else              { base = g_k + (size_t)(gwarp - nvec) * DK_; extra = 1.0f;   }
    float a = base[lane], b = base[lane + 32];
    float s = a * a + b * b;
    #pragma unroll
    for (int o = 16; o; o >>= 1) s += __shfl_xor_sync(0xffffffffu, s, o);
    float r = rsqrtf(s + 1e-6f) * extra;
    base[lane] = a * r;
    base[lane + 32] = b * r;
}

// ---------------- gated delta rule scan --------------------------------------
// block = (b,h,vhalf): 128 CTAs. 128 threads: thread = jloc*2 + kh.
// Thread owns S[kh*32 : kh*32+32][vhalf*64 + jloc]; pairs combine via shfl.
__global__ void __launch_bounds__(128)
delta_kernel() {
    int bh = blockIdx.x >> 1;
    int vh = blockIdx.x & 1;
    int b = bh >> 3, h = bh & 7;
    int tid = threadIdx.x;
    int jloc = tid >> 1;
    int kh   = tid & 1;
    int j = vh * 64 + jloc;
    const int kofs = kh * 32;

    __shared__ float sq[2][64], sk[2][64];
    float S[32];
    #pragma unroll
    for (int i = 0; i < 32; i++) S[i] = 0.f;

    const size_t tok0 = (size_t)b * T_ * H_ + h;
    const float* qb = g_q + tok0 * DK_;
    const float* kb = g_k + tok0 * DK_;
    const float* vb = g_v + tok0 * DV_;
    float*       ob = g_o + tok0 * DV_;
    const float* gb = g_g + tok0;
    const float* bbp = g_beta + tok0;

    if (tid < 64) sq[0][tid] = qb[tid]; else sk[0][tid - 64] = kb[tid - 64];
    float vcur = vb[j];
    float gcur = gb[0], bcur = bbp[0];
    __syncthreads();

    for (int t = 0; t < T_; t++) {
        int cur = t & 1, nxt = cur ^ 1;
        float vnext = 0.f, gnext = 0.f, bnext = 0.f;
        if (t + 1 < T_) {
            size_t off = (size_t)(t + 1) * H_;
            if (tid < 64) sq[nxt][tid] = qb[off * DK_ + tid];
            else          sk[nxt][tid - 64] = kb[off * DK_ + (tid - 64)];
            vnext = vb[off * DV_ + j];
            gnext = gb[off];
            bnext = bbp[off];
        }
        float eg = expf(gcur);

        float kk[32];
        #pragma unroll
        for (int i = 0; i < 32; i += 4) {
            float4 t4 = *(const float4*)&sk[cur][kofs + i];
            kk[i] = t4.x; kk[i+1] = t4.y; kk[i+2] = t4.z; kk[i+3] = t4.w;
        }
        float kv0 = 0.f, kv1 = 0.f, kv2 = 0.f, kv3 = 0.f;
        #pragma unroll
        for (int i = 0; i < 32; i += 4) {
            kv0 += S[i + 0] * kk[i + 0];
            kv1 += S[i + 1] * kk[i + 1];
            kv2 += S[i + 2] * kk[i + 2];
            kv3 += S[i + 3] * kk[i + 3];
        }
        float kv = (kv0 + kv1) + (kv2 + kv3);
        kv += __shfl_xor_sync(0xffffffffu, kv, 1);
        float vres = (vcur - eg * kv) * bcur;

        float o0 = 0.f, o1 = 0.f, o2 = 0.f, o3 = 0.f;
        #pragma unroll
        for (int i = 0; i < 32; i += 4) {
            float4 q4 = *(const float4*)&sq[cur][kofs + i];
            S[i + 0] = eg * S[i + 0] + kk[i + 0] * vres; o0 += S[i + 0] * q4.x;
            S[i + 1] = eg * S[i + 1] + kk[i + 1] * vres; o1 += S[i + 1] * q4.y;
            S[i + 2] = eg * S[i + 2] + kk[i + 2] * vres; o2 += S[i + 2] * q4.z;
            S[i + 3] = eg * S[i + 3] + kk[i + 3] * vres; o3 += S[i + 3] * q4.w;
        }
        float o = (o0 + o1) + (o2 + o3);
        o += __shfl_xor_sync(0xffffffffu, o, 1);
        if (kh == 0) ob[(size_t)t * H_ * DV_ + j] = o;

        vcur = vnext; gcur = gnext; bcur = bnext;
        __syncthreads();
    }
}

// ---------------- gated RMSNorm on o: rms(o)*w*silu(gate) --------------------
__global__ void gatednorm_kernel(const float* __restrict__ o_norm_w) {
    int gvec = blockIdx.x * 8 + (threadIdx.x >> 5);   // (row, h)
    int lane = threadIdx.x & 31;
    int row = gvec >> 3, h = gvec & 7;

    const float* obase = g_o + (size_t)row * VDIM_ + h * DV_;
    float4 ov = *(const float4*)(obase + lane * 4);
    float s = ov.x * ov.x + ov.y * ov.y + ov.z * ov.z + ov.w * ov.w;
    #pragma unroll
    for (int off = 16; off; off >>= 1) s += __shfl_xor_sync(0xffffffffu, s, off);
    float scale = rsqrtf(s * (1.0f / (float)DV_) + 1e-5f);

    const float* gptr = g_c1 + (size_t)row * M1 + 2064 + h * DV_ + lane * 4;
    float4 gv = *(const float4*)gptr;
    float4 wv = *(const float4*)(o_norm_w + lane * 4);
    float4 out;
    out.x = ov.x * scale * wv.x * (gv.x / (1.f + expf(-gv.x)));
    out.y = ov.y * scale * wv.y * (gv.y / (1.f + expf(-gv.y)));
    out.z = ov.z * scale * wv.z * (gv.z / (1.f + expf(-gv.z)));
    out.w = ov.w * scale * wv.w * (gv.w / (1.f + expf(-gv.w)));
    *(float4*)(g_og + (size_t)row * VDIM_ + h * DV_ + lane * 4) = out;
}

// ---------------- launch ------------------------------------------------------
static inline int cdiv(int a, int b) { return (a + b - 1) / b; }

extern "C" void kernel_launch(void* const* d_in, const int* in_sizes, int n_in,
                              void* d_out, int out_size) {
    const float* x       = (const float*)d_in[0];
    const float* Wq      = (const float*)d_in[1];
    const float* Wk      = (const float*)d_in[2];
    const float* Wv      = (const float*)d_in[3];
    const float* Wb      = (const float*)d_in[4];
    const float* Wa      = (const float*)d_in[5];
    const float* Wg      = (const float*)d_in[6];
    const float* Wo      = (const float*)d_in[7];
    const float* conv_q  = (const float*)d_in[8];
    const float* conv_k  = (const float*)d_in[9];
    const float* conv_v  = (const float*)d_in[10];
    const float* A_log   = (const float*)d_in[11];
    const float* dt_bias = (const float*)d_in[12];
    const float* o_norm_w= (const float*)d_in[13];
    const float* W_fc    = (const float*)d_in[14];
    const float* W_proj  = (const float*)d_in[15];
    const float* gdn_scale = (const float*)d_in[16];
    const float* mlp_scale = (const float*)d_in[17];
    float* out = (float*)d_out;

    float *p_h, *p_wcat, *p_c1, *p_xmid, *p_h2, *p_m2, *p_og;
    cudaGetSymbolAddress((void**)&p_h,    g_h);
    cudaGetSymbolAddress((void**)&p_wcat, g_wcat);
    cudaGetSymbolAddress((void**)&p_c1,   g_c1);
    cudaGetSymbolAddress((void**)&p_xmid, g_xmid);
    cudaGetSymbolAddress((void**)&p_h2,   g_h2);
    cudaGetSymbolAddress((void**)&p_m2,   g_m2);
    cudaGetSymbolAddress((void**)&p_og,   g_og);

    // 0) pack fused weights
    pack_wcat<<<cdiv(M1 * D_, 256), 256>>>(Wq, Wk, Wv, Wb, Wa, Wg);

    // 1) h = rmsnorm(x)
    rms_kernel<<<NTOK, D_>>>(x, p_h);

    // 2) C1 = h @ Wcat^T   (16384 x 3088), K=544
    tmma_gemm<<<dim3(cdiv(M1, 128), NTOK / 128), 256>>>(
        p_h, p_wcat, p_c1, M1, D_, 0, nullptr, nullptr);

    // 3) conv + silu  -> q,k,v
    conv_silu_kernel<<<cdiv(NTOK * 2048, 256), 256>>>(conv_q, conv_k, conv_v);

    // 4) beta, g
    betag_kernel<<<cdiv(NTOK * H_, 256), 256>>>(A_log, dt_bias);

    // 5) l2 norm q (with DK^-0.5), k
    l2_kernel<<<cdiv(NTOK * H_ * 2 * 32, 256), 256>>>();

    // 6) gated delta rule scan
    delta_kernel<<<B_ * H_ * 2, 128>>>();

    // 7) gated RMSNorm(o) * silu(gate)
    gatednorm_kernel<<<NTOK * H_ / 8, 256>>>(o_norm_w);

    // 8) x_mid = x + gdn_scale * (og @ Wo^T), K=1024
    tmma_gemm<<<dim3(cdiv(D_, 128), NTOK / 128), 256>>>(
        p_og, Wo, p_xmid, D_, VDIM_, 1, x, gdn_scale);

    // 9) h2 = rmsnorm(x_mid)
    rms_kernel<<<NTOK, D_>>>(p_xmid, p_h2);

    // 10) m2 = relu(h2 @ W_fc^T)^2, K=544
    tmma_gemm<<<dim3(cdiv(HID_, 128), NTOK / 128), 256>>>(
        p_h2, W_fc, p_m2, HID_, D_, 2, nullptr, nullptr);

    // 11) out = x_mid + mlp_scale * (m2 @ W_proj^T), K=1632
    tmma_gemm<<<dim3(cdiv(D_, 128), NTOK / 128), 256>>>(
        p_m2, W_proj, out, D_, HID_, 1, p_xmid, mlp_scale);
}